// round 9
// baseline (speedup 1.0000x reference)
#include <cuda_runtime.h>
#include <cuda_bf16.h>
#include <cuda_fp16.h>
#include <math.h>
#include <stdint.h>

#define N_NODES 100000
#define N_EDGES 1600000
#define F_IN 512
#define HID 156
#define N_CLS 7
#define NPAD 160
#define NP2 80          // half2 pairs per row
#define H2W 8           // padded row width of g_h2

// ---------------- scratch (device globals; no allocation allowed) ----------
__device__ __align__(16) __half g_h16[(size_t)N_NODES * NPAD];   // 32 MB, dis-scaled
__device__ __align__(16) float g_h2[(size_t)N_NODES * H2W];      // 3.2 MB, dis-scaled
__device__ float g_dis[N_NODES];
__device__ int   g_deg[N_NODES];
__device__ int   g_rowptr[N_NODES + 1];
__device__ int   g_cursor[N_NODES];
__device__ int   g_col[N_EDGES];
__device__ int   g_blocksums[128];
__device__ unsigned g_ticket;
__device__ __align__(16) __nv_bfloat16 g_wt_hi[NPAD * F_IN];   // W1^T hi, [160][512]
__device__ __align__(16) __nv_bfloat16 g_wt_lo[NPAD * F_IN];   // W1^T lo

#define SCAN_BLOCKS ((N_NODES + 1023) / 1024)    // 98

// ---------------- setup: W1 transpose/split + deg init + ticket reset -------
__global__ void k_setup(const float* __restrict__ W1) {
    int idx = blockIdx.x * 256 + threadIdx.x;
    if (idx == 0) g_ticket = 0;
    if (idx < NPAD * F_IN) {
        int n = idx >> 9;
        int k = idx & 511;
        float v = (n < HID) ? W1[(size_t)k * HID + n] : 0.f;
        __nv_bfloat16 hi = __float2bfloat16(v);
        __nv_bfloat16 lo = __float2bfloat16(v - __bfloat162float(hi));
        g_wt_hi[idx] = hi;
        g_wt_lo[idx] = lo;
    }
    if (idx < N_NODES) g_deg[idx] = 1;
}

// ---------------- degree / CSR build ---------------------------------------
__global__ void k_count(const int* __restrict__ dst) {
    int e = blockIdx.x * blockDim.x + threadIdx.x;
    if (e < N_EDGES) atomicAdd(&g_deg[dst[e]], 1);
}

// scan1: per-block inclusive scan; LAST block also exclusive-scans blocksums
__global__ void k_scan1() {
    __shared__ int sh[1024];
    __shared__ int isLast;
    int t = threadIdx.x;
    int i = blockIdx.x * 1024 + t;
    int v = (i < N_NODES) ? (g_deg[i] - 1) : 0;
    sh[t] = v;
    __syncthreads();
    for (int off = 1; off < 1024; off <<= 1) {
        int add = (t >= off) ? sh[t - off] : 0;
        __syncthreads();
        sh[t] += add;
        __syncthreads();
    }
    int incl = sh[t];
    if (i < N_NODES) g_rowptr[i] = incl - v;      // exclusive within block
    if (t == 1023) g_blocksums[blockIdx.x] = incl;
    __threadfence();
    if (t == 0) isLast = (atomicAdd(&g_ticket, 1) == gridDim.x - 1) ? 1 : 0;
    __syncthreads();
    if (isLast) {
        int bv = 0;
        if (t < 128) {
            bv = (t < SCAN_BLOCKS) ? __ldcg(&g_blocksums[t]) : 0;
            sh[t] = bv;
        }
        __syncthreads();
        for (int off = 1; off < 128; off <<= 1) {
            int add = (t >= off && t < 128) ? sh[t - off] : 0;
            __syncthreads();
            if (t < 128) sh[t] += add;
            __syncthreads();
        }
        if (t < SCAN_BLOCKS) g_blocksums[t] = sh[t] - bv;   // exclusive prefix
    }
}

// scan3m: elementwise add of pre-scanned blocksums + dis + cursor
__global__ void k_scan3m() {
    int i = blockIdx.x * 1024 + threadIdx.x;
    if (i < N_NODES) {
        int r = g_rowptr[i] + g_blocksums[i >> 10];
        g_rowptr[i] = r;
        g_cursor[i] = r;
        g_dis[i] = rsqrtf((float)g_deg[i]);
        if (i == 0) g_rowptr[N_NODES] = N_EDGES;
    }
}

// ---------------- GEMM1 (mma.sync bf16-split + ldmatrix) fused with fill ----
#define A_HI 0
#define A_LO 10240
#define B_HI 20480
#define B_LO 33280
#define SMEM_GEMM 46080

#define GEMM_BLOCKS ((N_NODES + 127) / 128)           // 782
#define FILL_BLOCKS ((N_EDGES + 255) / 256)           // 6250
#define FPG ((FILL_BLOCKS + GEMM_BLOCKS - 1) / GEMM_BLOCKS)   // 8
#define FUSED_GRID (GEMM_BLOCKS * (FPG + 1))          // 7038

__device__ __forceinline__ void mma16816(float* d, const uint32_t* a,
                                         uint32_t b0, uint32_t b1) {
    asm volatile(
        "mma.sync.aligned.m16n8k16.row.col.f32.bf16.bf16.f32 "
        "{%0,%1,%2,%3}, {%4,%5,%6,%7}, {%8,%9}, {%0,%1,%2,%3};"
        : "+f"(d[0]), "+f"(d[1]), "+f"(d[2]), "+f"(d[3])
        : "r"(a[0]), "r"(a[1]), "r"(a[2]), "r"(a[3]), "r"(b0), "r"(b1));
}
#define LDSM4(r, addr) \
    asm volatile("ldmatrix.sync.aligned.m8n8.x4.shared.b16 {%0,%1,%2,%3}, [%4];" \
        : "=r"((r)[0]), "=r"((r)[1]), "=r"((r)[2]), "=r"((r)[3]) : "r"(addr))

__global__ void __launch_bounds__(256) k_gemm_fill(const float* __restrict__ x,
                                                   const int* __restrict__ src,
                                                   const int* __restrict__ dst) {
    int grp = blockIdx.x / (FPG + 1);
    int rsl = blockIdx.x - grp * (FPG + 1);
    if (rsl != 0) {
        // ---- fill block: place edges into CSR ----
        int fb = grp * FPG + (rsl - 1);
        int e = fb * 256 + threadIdx.x;
        if (fb < FILL_BLOCKS && e < N_EDGES) {
            int d = __ldg(dst + e);
            int pos = atomicAdd(&g_cursor[d], 1);
            g_col[pos] = __ldg(src + e);
        }
        return;
    }

    extern __shared__ char smem[];
    int tid = threadIdx.x, wid = tid >> 5, lane = tid & 31;
    int g = lane >> 2, tg = lane & 3;
    int wm = wid & 3, wn = wid >> 2;
    int bm = grp * 128;

    uint32_t sbase = (uint32_t)__cvta_generic_to_shared(smem);
    int l8 = lane & 7;
    int aRow = l8 + ((lane >> 3) & 1) * 8;
    int aCol = (lane >= 16) ? 16 : 0;
    uint32_t aHiAddr = sbase + A_HI + (uint32_t)(wm * 32 + aRow) * 80 + aCol;
    uint32_t aLoAddr = sbase + A_LO + (uint32_t)(wm * 32 + aRow) * 80 + aCol;
    int bRow = l8 + ((lane >> 4) & 1) * 8;
    int bCol = ((lane >> 3) & 1) * 16;
    uint32_t bHiAddr = sbase + B_HI + (uint32_t)(wn * 80 + bRow) * 80 + bCol;
    uint32_t bLoAddr = sbase + B_LO + (uint32_t)(wn * 80 + bRow) * 80 + bCol;

    float acc[2][10][4];
#pragma unroll
    for (int i = 0; i < 2; i++)
#pragma unroll
        for (int j = 0; j < 10; j++)
#pragma unroll
            for (int q = 0; q < 4; q++) acc[i][j][q] = 0.f;

    float4 pa[4];
    uint2  pbh[5], pbl[5];

#pragma unroll
    for (int j = 0; j < 4; j++) {
        int idx = tid + j * 256;
        int r = idx >> 3, f4 = idx & 7;
        pa[j] = make_float4(0.f, 0.f, 0.f, 0.f);
        if (bm + r < N_NODES)
            pa[j] = *(const float4*)(x + (size_t)(bm + r) * F_IN + f4 * 4);
    }
#pragma unroll
    for (int j = 0; j < 5; j++) {
        int idx = tid + j * 256;
        int n = idx >> 3, q = idx & 7;
        pbh[j] = *(const uint2*)((const char*)g_wt_hi + (size_t)n * 1024 + q * 8);
        pbl[j] = *(const uint2*)((const char*)g_wt_lo + (size_t)n * 1024 + q * 8);
    }

#pragma unroll
    for (int j = 0; j < 4; j++) {
        int idx = tid + j * 256;
        int r = idx >> 3, f4 = idx & 7;
        float4 v = pa[j];
        __nv_bfloat162 h01 = __floats2bfloat162_rn(v.x, v.y);
        __nv_bfloat162 h23 = __floats2bfloat162_rn(v.z, v.w);
        __nv_bfloat162 l01 = __floats2bfloat162_rn(
            v.x - __bfloat162float(__low2bfloat16(h01)),
            v.y - __bfloat162float(__high2bfloat16(h01)));
        __nv_bfloat162 l23 = __floats2bfloat162_rn(
            v.z - __bfloat162float(__low2bfloat16(h23)),
            v.w - __bfloat162float(__high2bfloat16(h23)));
        uint2 hw, lw;
        hw.x = *(uint32_t*)&h01; hw.y = *(uint32_t*)&h23;
        lw.x = *(uint32_t*)&l01; lw.y = *(uint32_t*)&l23;
        *(uint2*)(smem + A_HI + r * 80 + f4 * 8) = hw;
        *(uint2*)(smem + A_LO + r * 80 + f4 * 8) = lw;
    }
#pragma unroll
    for (int j = 0; j < 5; j++) {
        int idx = tid + j * 256;
        int n = idx >> 3, q = idx & 7;
        *(uint2*)(smem + B_HI + n * 80 + q * 8) = pbh[j];
        *(uint2*)(smem + B_LO + n * 80 + q * 8) = pbl[j];
    }
    __syncthreads();

#pragma unroll 1
    for (int c = 0; c < 16; c++) {
        if (c + 1 < 16) {
            int k0 = (c + 1) * 32;
#pragma unroll
            for (int j = 0; j < 4; j++) {
                int idx = tid + j * 256;
                int r = idx >> 3, f4 = idx & 7;
                pa[j] = make_float4(0.f, 0.f, 0.f, 0.f);
                if (bm + r < N_NODES)
                    pa[j] = *(const float4*)(x + (size_t)(bm + r) * F_IN + k0 + f4 * 4);
            }
#pragma unroll
            for (int j = 0; j < 5; j++) {
                int idx = tid + j * 256;
                int n = idx >> 3, q = idx & 7;
                pbh[j] = *(const uint2*)((const char*)g_wt_hi + (size_t)n * 1024 + k0 * 2 + q * 8);
                pbl[j] = *(const uint2*)((const char*)g_wt_lo + (size_t)n * 1024 + k0 * 2 + q * 8);
            }
        }

#pragma unroll
        for (int kk = 0; kk < 2; kk++) {
            int kb = kk * 32;
            uint32_t ah[2][4], al[2][4];
#pragma unroll
            for (int mf = 0; mf < 2; mf++) {
                LDSM4(ah[mf], aHiAddr + mf * 1280 + kb);
                LDSM4(al[mf], aLoAddr + mf * 1280 + kb);
            }
#pragma unroll
            for (int pnf = 0; pnf < 5; pnf++) {
                uint32_t bh[4], bl[4];
                LDSM4(bh, bHiAddr + pnf * 1280 + kb);
                LDSM4(bl, bLoAddr + pnf * 1280 + kb);
#pragma unroll
                for (int mf = 0; mf < 2; mf++) {
                    mma16816(acc[mf][2 * pnf],     ah[mf], bh[0], bh[1]);
                    mma16816(acc[mf][2 * pnf],     ah[mf], bl[0], bl[1]);
                    mma16816(acc[mf][2 * pnf],     al[mf], bh[0], bh[1]);
                    mma16816(acc[mf][2 * pnf + 1], ah[mf], bh[2], bh[3]);
                    mma16816(acc[mf][2 * pnf + 1], ah[mf], bl[2], bl[3]);
                    mma16816(acc[mf][2 * pnf + 1], al[mf], bh[2], bh[3]);
                }
            }
        }
        __syncthreads();

        if (c + 1 < 16) {
#pragma unroll
            for (int j = 0; j < 4; j++) {
                int idx = tid + j * 256;
                int r = idx >> 3, f4 = idx & 7;
                float4 v = pa[j];
                __nv_bfloat162 h01 = __floats2bfloat162_rn(v.x, v.y);
                __nv_bfloat162 h23 = __floats2bfloat162_rn(v.z, v.w);
                __nv_bfloat162 l01 = __floats2bfloat162_rn(
                    v.x - __bfloat162float(__low2bfloat16(h01)),
                    v.y - __bfloat162float(__high2bfloat16(h01)));
                __nv_bfloat162 l23 = __floats2bfloat162_rn(
                    v.z - __bfloat162float(__low2bfloat16(h23)),
                    v.w - __bfloat162float(__high2bfloat16(h23)));
                uint2 hw, lw;
                hw.x = *(uint32_t*)&h01; hw.y = *(uint32_t*)&h23;
                lw.x = *(uint32_t*)&l01; lw.y = *(uint32_t*)&l23;
                *(uint2*)(smem + A_HI + r * 80 + f4 * 8) = hw;
                *(uint2*)(smem + A_LO + r * 80 + f4 * 8) = lw;
            }
#pragma unroll
            for (int j = 0; j < 5; j++) {
                int idx = tid + j * 256;
                int n = idx >> 3, q = idx & 7;
                *(uint2*)(smem + B_HI + n * 80 + q * 8) = pbh[j];
                *(uint2*)(smem + B_LO + n * 80 + q * 8) = pbl[j];
            }
            __syncthreads();
        }
    }

    // ---- epilogue: scale by dis, half2 pack -> smem -> uint4 stores ----
    uint32_t* Hs = (uint32_t*)smem;
#pragma unroll
    for (int mf = 0; mf < 2; mf++) {
        int r = wm * 32 + mf * 16 + g;
        float d0 = (bm + r < N_NODES) ? g_dis[bm + r] : 0.f;
        float d8 = (bm + r + 8 < N_NODES) ? g_dis[bm + r + 8] : 0.f;
#pragma unroll
        for (int nf = 0; nf < 10; nf++) {
            int p = wn * 40 + nf * 4 + tg;
            __half2 v0 = __floats2half2_rn(acc[mf][nf][0] * d0, acc[mf][nf][1] * d0);
            __half2 v8 = __floats2half2_rn(acc[mf][nf][2] * d8, acc[mf][nf][3] * d8);
            Hs[r * 84 + p]       = *(uint32_t*)&v0;
            Hs[(r + 8) * 84 + p] = *(uint32_t*)&v8;
        }
    }
    __syncthreads();

    int rows = N_NODES - bm;
    if (rows > 128) rows = 128;
    int total4 = rows * 20;
    for (int i = tid; i < total4; i += 256) {
        int r = i / 20, q = i - r * 20;
        uint4 v = *(uint4*)&Hs[r * 84 + q * 4];
        *(uint4*)((char*)g_h16 + (size_t)(bm + r) * 320 + q * 16) = v;
    }
}

// ---------------- Agg1: gather dis-scaled h (fp16) + relu + W2 projection ---
__global__ void __launch_bounds__(256) k_agg1(const float* __restrict__ b1,
                                              const float* __restrict__ W2) {
    __shared__ float2 W2p[96 * N_CLS];
    __shared__ float2 b1p[96];
    int tid = threadIdx.x;
    for (int i = tid; i < 96 * N_CLS; i += 256) {
        int p = i / N_CLS, k = i - p * N_CLS;
        float lo = (2 * p < HID) ? W2[(2 * p) * N_CLS + k] : 0.f;
        float hi = (2 * p + 1 < HID) ? W2[(2 * p + 1) * N_CLS + k] : 0.f;
        W2p[i] = make_float2(lo, hi);
    }
    for (int p = tid; p < 96; p += 256) {
        float lo = (2 * p < HID) ? b1[2 * p] : 0.f;
        float hi = (2 * p + 1 < HID) ? b1[2 * p + 1] : 0.f;
        b1p[p] = make_float2(lo, hi);
    }
    __syncthreads();

    int warp = tid >> 5, lane = tid & 31;
    int node = blockIdx.x * 8 + warp;
    if (node >= N_NODES) return;

    float2 a0 = make_float2(0.f, 0.f), a1 = a0, a2 = a0;
    int beg = g_rowptr[node], end = g_rowptr[node + 1];
    const uint32_t* __restrict__ hbase = (const uint32_t*)g_h16;
    const int* __restrict__ colp = g_col;
#pragma unroll 2
    for (int e = beg; e < end; e++) {
        int s = __ldg(colp + e);
        const uint32_t* hp = hbase + (size_t)s * NP2;
        uint32_t w0 = __ldg(hp + lane);
        uint32_t w1 = __ldg(hp + lane + 32);
        uint32_t w2 = (lane < 16) ? __ldg(hp + lane + 64) : 0u;
        float2 f0 = __half22float2(*(__half2*)&w0);
        float2 f1 = __half22float2(*(__half2*)&w1);
        float2 f2 = __half22float2(*(__half2*)&w2);
        a0.x += f0.x; a0.y += f0.y;
        a1.x += f1.x; a1.y += f1.y;
        a2.x += f2.x; a2.y += f2.y;
    }
    {
        const uint32_t* hp = hbase + (size_t)node * NP2;
        uint32_t w0 = hp[lane];
        uint32_t w1 = hp[lane + 32];
        uint32_t w2 = (lane < 16) ? hp[lane + 64] : 0u;
        float2 f0 = __half22float2(*(__half2*)&w0);
        float2 f1 = __half22float2(*(__half2*)&w1);
        float2 f2 = __half22float2(*(__half2*)&w2);
        a0.x += f0.x; a0.y += f0.y;
        a1.x += f1.x; a1.y += f1.y;
        a2.x += f2.x; a2.y += f2.y;
    }
    float di = g_dis[node];
    float2 bb0 = b1p[lane], bb1 = b1p[lane + 32], bb2 = b1p[lane + 64];
    float2 u0 = make_float2(fmaxf(fmaf(di, a0.x, bb0.x), 0.f),
                            fmaxf(fmaf(di, a0.y, bb0.y), 0.f));
    float2 u1 = make_float2(fmaxf(fmaf(di, a1.x, bb1.x), 0.f),
                            fmaxf(fmaf(di, a1.y, bb1.y), 0.f));
    float2 u2 = make_float2(fmaxf(fmaf(di, a2.x, bb2.x), 0.f),
                            fmaxf(fmaf(di, a2.y, bb2.y), 0.f));
    if (lane >= 16) { u2.x = 0.f; u2.y = 0.f; }

    float outk[N_CLS];
#pragma unroll
    for (int k = 0; k < N_CLS; k++) {
        float2 w0 = W2p[lane * N_CLS + k];
        float2 w1 = W2p[(lane + 32) * N_CLS + k];
        float2 w2 = W2p[(lane + 64) * N_CLS + k];
        float p = u0.x * w0.x + u0.y * w0.y
                + u1.x * w1.x + u1.y * w1.y
                + u2.x * w2.x + u2.y * w2.y;
#pragma unroll
        for (int o = 16; o > 0; o >>= 1) p += __shfl_xor_sync(0xffffffffu, p, o);
        outk[k] = p;
    }
    if (lane == 0) {
#pragma unroll
        for (int k = 0; k < N_CLS; k++)
            g_h2[(size_t)node * H2W + k] = di * outk[k];
    }
}

// ---------------- Agg2 + bias + log_softmax ---------------------------------
__global__ void __launch_bounds__(256) k_agg2(const float* __restrict__ b2,
                                              float* __restrict__ out) {
    int i = blockIdx.x * blockDim.x + threadIdx.x;
    if (i >= N_NODES) return;

    float a0 = 0.f, a1 = 0.f, a2 = 0.f, a3 = 0.f, a4 = 0.f, a5 = 0.f, a6 = 0.f;

    int beg = g_rowptr[i], end = g_rowptr[i + 1];
    const int* __restrict__ colp = g_col;
#pragma unroll 2
    for (int e = beg; e < end; e++) {
        int s = __ldg(colp + e);
        const float4* p = (const float4*)(g_h2 + (size_t)s * H2W);
        float4 A = __ldg(p);
        float4 B = __ldg(p + 1);
        a0 += A.x; a1 += A.y; a2 += A.z; a3 += A.w;
        a4 += B.x; a5 += B.y; a6 += B.z;
    }
    {
        const float4* p = (const float4*)(g_h2 + (size_t)i * H2W);
        float4 A = *p;
        float4 B = *(p + 1);
        a0 += A.x; a1 += A.y; a2 += A.z; a3 += A.w;
        a4 += B.x; a5 += B.y; a6 += B.z;
    }
    float di = g_dis[i];
    float v[N_CLS];
    v[0] = fmaf(di, a0, __ldg(b2 + 0));
    v[1] = fmaf(di, a1, __ldg(b2 + 1));
    v[2] = fmaf(di, a2, __ldg(b2 + 2));
    v[3] = fmaf(di, a3, __ldg(b2 + 3));
    v[4] = fmaf(di, a4, __ldg(b2 + 4));
    v[5] = fmaf(di, a5, __ldg(b2 + 5));
    v[6] = fmaf(di, a6, __ldg(b2 + 6));

    float m = v[0];
#pragma unroll
    for (int k = 1; k < N_CLS; k++) m = fmaxf(m, v[k]);
    float s = 0.f;
#pragma unroll
    for (int k = 0; k < N_CLS; k++) s += expf(v[k] - m);
    float lse = m + logf(s);
#pragma unroll
    for (int k = 0; k < N_CLS; k++) out[(size_t)i * N_CLS + k] = v[k] - lse;
}

// ---------------- launch -----------------------------------------------------
extern "C" void kernel_launch(void* const* d_in, const int* in_sizes, int n_in,
                              void* d_out, int out_size) {
    const float* x  = (const float*)d_in[0];
    const int*   ei = (const int*)d_in[1];
    const float* W1 = (const float*)d_in[2];
    const float* b1 = (const float*)d_in[3];
    const float* W2 = (const float*)d_in[4];
    const float* b2 = (const float*)d_in[5];
    float* out = (float*)d_out;

    const int* src = ei;
    const int* dst = ei + N_EDGES;

    cudaFuncSetAttribute(k_gemm_fill, cudaFuncAttributeMaxDynamicSharedMemorySize, SMEM_GEMM);

    k_setup<<<(N_NODES + 255) / 256, 256>>>(W1);                   // 0
    k_count<<<(N_EDGES + 255) / 256, 256>>>(dst);                  // 1
    k_scan1<<<SCAN_BLOCKS, 1024>>>();                              // 2
    k_scan3m<<<SCAN_BLOCKS, 1024>>>();                             // 3
    k_gemm_fill<<<FUSED_GRID, 256, SMEM_GEMM>>>(x, src, dst);      // 4
    k_agg1<<<(N_NODES + 7) / 8, 256>>>(b1, W2);                    // 5
    k_agg2<<<(N_NODES + 255) / 256, 256>>>(b2, out);               // 6
}

// round 10
// speedup vs baseline: 1.0799x; 1.0799x over previous
#include <cuda_runtime.h>
#include <cuda_bf16.h>
#include <cuda_fp16.h>
#include <math.h>
#include <stdint.h>

#define N_NODES 100000
#define N_EDGES 1600000
#define F_IN 512
#define HID 156
#define N_CLS 7
#define NPAD 160
#define NP2 80          // half2 pairs per row
#define H2W 8           // padded row width of g_h2

// ---------------- scratch (device globals; no allocation allowed) ----------
__device__ __align__(16) __half g_h16[(size_t)N_NODES * NPAD];   // 32 MB, dis-scaled
__device__ __align__(16) float g_h2[(size_t)N_NODES * H2W];      // 3.2 MB, dis-scaled
__device__ float g_dis[N_NODES];
__device__ int   g_deg[N_NODES];
__device__ int   g_rowptr[N_NODES + 1];
__device__ int   g_cursor[N_NODES];
__device__ int   g_col[N_EDGES];
__device__ int   g_blocksums[128];
__device__ unsigned g_ticket;
__device__ __align__(16) __nv_bfloat16 g_wt_hi[NPAD * F_IN];   // W1^T hi, [160][512]
__device__ __align__(16) __nv_bfloat16 g_wt_lo[NPAD * F_IN];   // W1^T lo

#define SCAN_BLOCKS ((N_NODES + 1023) / 1024)    // 98

// ---------------- setup: W1 transpose/split + deg init + ticket reset -------
__global__ void k_setup(const float* __restrict__ W1) {
    int idx = blockIdx.x * 256 + threadIdx.x;
    if (idx == 0) g_ticket = 0;
    if (idx < NPAD * F_IN) {
        int n = idx >> 9;
        int k = idx & 511;
        float v = (n < HID) ? W1[(size_t)k * HID + n] : 0.f;
        __nv_bfloat16 hi = __float2bfloat16(v);
        __nv_bfloat16 lo = __float2bfloat16(v - __bfloat162float(hi));
        g_wt_hi[idx] = hi;
        g_wt_lo[idx] = lo;
    }
    if (idx < N_NODES) g_deg[idx] = 1;
}

// ---------------- degree / CSR build ---------------------------------------
__global__ void k_count(const int* __restrict__ dst) {
    int e = blockIdx.x * blockDim.x + threadIdx.x;
    if (e < N_EDGES) atomicAdd(&g_deg[__ldg(dst + e)], 1);
}

// scan1: per-block inclusive scan; LAST block also exclusive-scans blocksums
__global__ void k_scan1() {
    __shared__ int sh[1024];
    __shared__ int isLast;
    int t = threadIdx.x;
    int i = blockIdx.x * 1024 + t;
    int v = (i < N_NODES) ? (g_deg[i] - 1) : 0;
    sh[t] = v;
    __syncthreads();
    for (int off = 1; off < 1024; off <<= 1) {
        int add = (t >= off) ? sh[t - off] : 0;
        __syncthreads();
        sh[t] += add;
        __syncthreads();
    }
    int incl = sh[t];
    if (i < N_NODES) g_rowptr[i] = incl - v;      // exclusive within block
    if (t == 1023) g_blocksums[blockIdx.x] = incl;
    __threadfence();
    if (t == 0) isLast = (atomicAdd(&g_ticket, 1) == gridDim.x - 1) ? 1 : 0;
    __syncthreads();
    if (isLast) {
        int bv = 0;
        if (t < 128) {
            bv = (t < SCAN_BLOCKS) ? __ldcg(&g_blocksums[t]) : 0;
            sh[t] = bv;
        }
        __syncthreads();
        for (int off = 1; off < 128; off <<= 1) {
            int add = (t >= off && t < 128) ? sh[t - off] : 0;
            __syncthreads();
            if (t < 128) sh[t] += add;
            __syncthreads();
        }
        if (t < SCAN_BLOCKS) g_blocksums[t] = sh[t] - bv;   // exclusive prefix
    }
}

// scan3m: elementwise add of pre-scanned blocksums + dis + cursor
__global__ void k_scan3m() {
    int i = blockIdx.x * 1024 + threadIdx.x;
    if (i < N_NODES) {
        int r = g_rowptr[i] + g_blocksums[i >> 10];
        g_rowptr[i] = r;
        g_cursor[i] = r;
        g_dis[i] = rsqrtf((float)g_deg[i]);
        if (i == 0) g_rowptr[N_NODES] = N_EDGES;
    }
}

__global__ void k_fill(const int* __restrict__ src, const int* __restrict__ dst) {
    int e = blockIdx.x * blockDim.x + threadIdx.x;
    if (e < N_EDGES) {
        int d = __ldg(dst + e);
        int pos = atomicAdd(&g_cursor[d], 1);
        g_col[pos] = __ldg(src + e);
    }
}

// ---------------- GEMM1 via mma.sync bf16-split + ldmatrix ------------------
#define A_HI 0
#define A_LO 10240
#define B_HI 20480
#define B_LO 33280
#define SMEM_GEMM 46080

__device__ __forceinline__ void mma16816(float* d, const uint32_t* a,
                                         uint32_t b0, uint32_t b1) {
    asm volatile(
        "mma.sync.aligned.m16n8k16.row.col.f32.bf16.bf16.f32 "
        "{%0,%1,%2,%3}, {%4,%5,%6,%7}, {%8,%9}, {%0,%1,%2,%3};"
        : "+f"(d[0]), "+f"(d[1]), "+f"(d[2]), "+f"(d[3])
        : "r"(a[0]), "r"(a[1]), "r"(a[2]), "r"(a[3]), "r"(b0), "r"(b1));
}
#define LDSM4(r, addr) \
    asm volatile("ldmatrix.sync.aligned.m8n8.x4.shared.b16 {%0,%1,%2,%3}, [%4];" \
        : "=r"((r)[0]), "=r"((r)[1]), "=r"((r)[2]), "=r"((r)[3]) : "r"(addr))

__global__ void __launch_bounds__(256) k_gemm_mma(const float* __restrict__ x) {
    extern __shared__ char smem[];
    int tid = threadIdx.x, wid = tid >> 5, lane = tid & 31;
    int g = lane >> 2, tg = lane & 3;
    int wm = wid & 3, wn = wid >> 2;
    int bm = blockIdx.x * 128;

    uint32_t sbase = (uint32_t)__cvta_generic_to_shared(smem);
    int l8 = lane & 7;
    int aRow = l8 + ((lane >> 3) & 1) * 8;
    int aCol = (lane >= 16) ? 16 : 0;
    uint32_t aHiAddr = sbase + A_HI + (uint32_t)(wm * 32 + aRow) * 80 + aCol;
    uint32_t aLoAddr = sbase + A_LO + (uint32_t)(wm * 32 + aRow) * 80 + aCol;
    int bRow = l8 + ((lane >> 4) & 1) * 8;
    int bCol = ((lane >> 3) & 1) * 16;
    uint32_t bHiAddr = sbase + B_HI + (uint32_t)(wn * 80 + bRow) * 80 + bCol;
    uint32_t bLoAddr = sbase + B_LO + (uint32_t)(wn * 80 + bRow) * 80 + bCol;

    float acc[2][10][4];
#pragma unroll
    for (int i = 0; i < 2; i++)
#pragma unroll
        for (int j = 0; j < 10; j++)
#pragma unroll
            for (int q = 0; q < 4; q++) acc[i][j][q] = 0.f;

    float4 pa[4];
    uint2  pbh[5], pbl[5];

#pragma unroll
    for (int j = 0; j < 4; j++) {
        int idx = tid + j * 256;
        int r = idx >> 3, f4 = idx & 7;
        pa[j] = make_float4(0.f, 0.f, 0.f, 0.f);
        if (bm + r < N_NODES)
            pa[j] = *(const float4*)(x + (size_t)(bm + r) * F_IN + f4 * 4);
    }
#pragma unroll
    for (int j = 0; j < 5; j++) {
        int idx = tid + j * 256;
        int n = idx >> 3, q = idx & 7;
        pbh[j] = *(const uint2*)((const char*)g_wt_hi + (size_t)n * 1024 + q * 8);
        pbl[j] = *(const uint2*)((const char*)g_wt_lo + (size_t)n * 1024 + q * 8);
    }

#pragma unroll
    for (int j = 0; j < 4; j++) {
        int idx = tid + j * 256;
        int r = idx >> 3, f4 = idx & 7;
        float4 v = pa[j];
        __nv_bfloat162 h01 = __floats2bfloat162_rn(v.x, v.y);
        __nv_bfloat162 h23 = __floats2bfloat162_rn(v.z, v.w);
        __nv_bfloat162 l01 = __floats2bfloat162_rn(
            v.x - __bfloat162float(__low2bfloat16(h01)),
            v.y - __bfloat162float(__high2bfloat16(h01)));
        __nv_bfloat162 l23 = __floats2bfloat162_rn(
            v.z - __bfloat162float(__low2bfloat16(h23)),
            v.w - __bfloat162float(__high2bfloat16(h23)));
        uint2 hw, lw;
        hw.x = *(uint32_t*)&h01; hw.y = *(uint32_t*)&h23;
        lw.x = *(uint32_t*)&l01; lw.y = *(uint32_t*)&l23;
        *(uint2*)(smem + A_HI + r * 80 + f4 * 8) = hw;
        *(uint2*)(smem + A_LO + r * 80 + f4 * 8) = lw;
    }
#pragma unroll
    for (int j = 0; j < 5; j++) {
        int idx = tid + j * 256;
        int n = idx >> 3, q = idx & 7;
        *(uint2*)(smem + B_HI + n * 80 + q * 8) = pbh[j];
        *(uint2*)(smem + B_LO + n * 80 + q * 8) = pbl[j];
    }
    __syncthreads();

#pragma unroll 1
    for (int c = 0; c < 16; c++) {
        if (c + 1 < 16) {
            int k0 = (c + 1) * 32;
#pragma unroll
            for (int j = 0; j < 4; j++) {
                int idx = tid + j * 256;
                int r = idx >> 3, f4 = idx & 7;
                pa[j] = make_float4(0.f, 0.f, 0.f, 0.f);
                if (bm + r < N_NODES)
                    pa[j] = *(const float4*)(x + (size_t)(bm + r) * F_IN + k0 + f4 * 4);
            }
#pragma unroll
            for (int j = 0; j < 5; j++) {
                int idx = tid + j * 256;
                int n = idx >> 3, q = idx & 7;
                pbh[j] = *(const uint2*)((const char*)g_wt_hi + (size_t)n * 1024 + k0 * 2 + q * 8);
                pbl[j] = *(const uint2*)((const char*)g_wt_lo + (size_t)n * 1024 + k0 * 2 + q * 8);
            }
        }

#pragma unroll
        for (int kk = 0; kk < 2; kk++) {
            int kb = kk * 32;
            uint32_t ah[2][4], al[2][4];
#pragma unroll
            for (int mf = 0; mf < 2; mf++) {
                LDSM4(ah[mf], aHiAddr + mf * 1280 + kb);
                LDSM4(al[mf], aLoAddr + mf * 1280 + kb);
            }
#pragma unroll
            for (int pnf = 0; pnf < 5; pnf++) {
                uint32_t bh[4], bl[4];
                LDSM4(bh, bHiAddr + pnf * 1280 + kb);
                LDSM4(bl, bLoAddr + pnf * 1280 + kb);
#pragma unroll
                for (int mf = 0; mf < 2; mf++) {
                    mma16816(acc[mf][2 * pnf],     ah[mf], bh[0], bh[1]);
                    mma16816(acc[mf][2 * pnf],     ah[mf], bl[0], bl[1]);
                    mma16816(acc[mf][2 * pnf],     al[mf], bh[0], bh[1]);
                    mma16816(acc[mf][2 * pnf + 1], ah[mf], bh[2], bh[3]);
                    mma16816(acc[mf][2 * pnf + 1], ah[mf], bl[2], bl[3]);
                    mma16816(acc[mf][2 * pnf + 1], al[mf], bh[2], bh[3]);
                }
            }
        }
        __syncthreads();

        if (c + 1 < 16) {
#pragma unroll
            for (int j = 0; j < 4; j++) {
                int idx = tid + j * 256;
                int r = idx >> 3, f4 = idx & 7;
                float4 v = pa[j];
                __nv_bfloat162 h01 = __floats2bfloat162_rn(v.x, v.y);
                __nv_bfloat162 h23 = __floats2bfloat162_rn(v.z, v.w);
                __nv_bfloat162 l01 = __floats2bfloat162_rn(
                    v.x - __bfloat162float(__low2bfloat16(h01)),
                    v.y - __bfloat162float(__high2bfloat16(h01)));
                __nv_bfloat162 l23 = __floats2bfloat162_rn(
                    v.z - __bfloat162float(__low2bfloat16(h23)),
                    v.w - __bfloat162float(__high2bfloat16(h23)));
                uint2 hw, lw;
                hw.x = *(uint32_t*)&h01; hw.y = *(uint32_t*)&h23;
                lw.x = *(uint32_t*)&l01; lw.y = *(uint32_t*)&l23;
                *(uint2*)(smem + A_HI + r * 80 + f4 * 8) = hw;
                *(uint2*)(smem + A_LO + r * 80 + f4 * 8) = lw;
            }
#pragma unroll
            for (int j = 0; j < 5; j++) {
                int idx = tid + j * 256;
                int n = idx >> 3, q = idx & 7;
                *(uint2*)(smem + B_HI + n * 80 + q * 8) = pbh[j];
                *(uint2*)(smem + B_LO + n * 80 + q * 8) = pbl[j];
            }
            __syncthreads();
        }
    }

    // ---- epilogue: scale by dis, half2 pack -> smem -> uint4 stores ----
    uint32_t* Hs = (uint32_t*)smem;
#pragma unroll
    for (int mf = 0; mf < 2; mf++) {
        int r = wm * 32 + mf * 16 + g;
        float d0 = (bm + r < N_NODES) ? g_dis[bm + r] : 0.f;
        float d8 = (bm + r + 8 < N_NODES) ? g_dis[bm + r + 8] : 0.f;
#pragma unroll
        for (int nf = 0; nf < 10; nf++) {
            int p = wn * 40 + nf * 4 + tg;
            __half2 v0 = __floats2half2_rn(acc[mf][nf][0] * d0, acc[mf][nf][1] * d0);
            __half2 v8 = __floats2half2_rn(acc[mf][nf][2] * d8, acc[mf][nf][3] * d8);
            Hs[r * 84 + p]       = *(uint32_t*)&v0;
            Hs[(r + 8) * 84 + p] = *(uint32_t*)&v8;
        }
    }
    __syncthreads();

    int rows = N_NODES - bm;
    if (rows > 128) rows = 128;
    int total4 = rows * 20;
    for (int i = tid; i < total4; i += 256) {
        int r = i / 20, q = i - r * 20;
        uint4 v = *(uint4*)&Hs[r * 84 + q * 4];
        *(uint4*)((char*)g_h16 + (size_t)(bm + r) * 320 + q * 16) = v;
    }
}

// ---------------- Agg1: gather dis-scaled h (fp16) + relu + W2 projection ---
__global__ void __launch_bounds__(256) k_agg1(const float* __restrict__ b1,
                                              const float* __restrict__ W2) {
    __shared__ float2 W2p[96 * N_CLS];
    __shared__ float2 b1p[96];
    int tid = threadIdx.x;
    for (int i = tid; i < 96 * N_CLS; i += 256) {
        int p = i / N_CLS, k = i - p * N_CLS;
        float lo = (2 * p < HID) ? W2[(2 * p) * N_CLS + k] : 0.f;
        float hi = (2 * p + 1 < HID) ? W2[(2 * p + 1) * N_CLS + k] : 0.f;
        W2p[i] = make_float2(lo, hi);
    }
    for (int p = tid; p < 96; p += 256) {
        float lo = (2 * p < HID) ? b1[2 * p] : 0.f;
        float hi = (2 * p + 1 < HID) ? b1[2 * p + 1] : 0.f;
        b1p[p] = make_float2(lo, hi);
    }
    __syncthreads();

    int warp = tid >> 5, lane = tid & 31;
    int node = blockIdx.x * 8 + warp;
    if (node >= N_NODES) return;

    float2 a0 = make_float2(0.f, 0.f), a1 = a0, a2 = a0;
    int beg = g_rowptr[node], end = g_rowptr[node + 1];
    const uint32_t* __restrict__ hbase = (const uint32_t*)g_h16;
    const int* __restrict__ colp = g_col;
#pragma unroll 2
    for (int e = beg; e < end; e++) {
        int s = __ldg(colp + e);
        const uint32_t* hp = hbase + (size_t)s * NP2;
        uint32_t w0 = __ldg(hp + lane);
        uint32_t w1 = __ldg(hp + lane + 32);
        uint32_t w2 = (lane < 16) ? __ldg(hp + lane + 64) : 0u;
        float2 f0 = __half22float2(*(__half2*)&w0);
        float2 f1 = __half22float2(*(__half2*)&w1);
        float2 f2 = __half22float2(*(__half2*)&w2);
        a0.x += f0.x; a0.y += f0.y;
        a1.x += f1.x; a1.y += f1.y;
        a2.x += f2.x; a2.y += f2.y;
    }
    {
        const uint32_t* hp = hbase + (size_t)node * NP2;
        uint32_t w0 = hp[lane];
        uint32_t w1 = hp[lane + 32];
        uint32_t w2 = (lane < 16) ? hp[lane + 64] : 0u;
        float2 f0 = __half22float2(*(__half2*)&w0);
        float2 f1 = __half22float2(*(__half2*)&w1);
        float2 f2 = __half22float2(*(__half2*)&w2);
        a0.x += f0.x; a0.y += f0.y;
        a1.x += f1.x; a1.y += f1.y;
        a2.x += f2.x; a2.y += f2.y;
    }
    float di = g_dis[node];
    float2 bb0 = b1p[lane], bb1 = b1p[lane + 32], bb2 = b1p[lane + 64];
    float2 u0 = make_float2(fmaxf(fmaf(di, a0.x, bb0.x), 0.f),
                            fmaxf(fmaf(di, a0.y, bb0.y), 0.f));
    float2 u1 = make_float2(fmaxf(fmaf(di, a1.x, bb1.x), 0.f),
                            fmaxf(fmaf(di, a1.y, bb1.y), 0.f));
    float2 u2 = make_float2(fmaxf(fmaf(di, a2.x, bb2.x), 0.f),
                            fmaxf(fmaf(di, a2.y, bb2.y), 0.f));
    if (lane >= 16) { u2.x = 0.f; u2.y = 0.f; }

    float outk[N_CLS];
#pragma unroll
    for (int k = 0; k < N_CLS; k++) {
        float2 w0 = W2p[lane * N_CLS + k];
        float2 w1 = W2p[(lane + 32) * N_CLS + k];
        float2 w2 = W2p[(lane + 64) * N_CLS + k];
        float p = u0.x * w0.x + u0.y * w0.y
                + u1.x * w1.x + u1.y * w1.y
                + u2.x * w2.x + u2.y * w2.y;
#pragma unroll
        for (int o = 16; o > 0; o >>= 1) p += __shfl_xor_sync(0xffffffffu, p, o);
        outk[k] = p;
    }
    if (lane == 0) {
#pragma unroll
        for (int k = 0; k < N_CLS; k++)
            g_h2[(size_t)node * H2W + k] = di * outk[k];
    }
}

// ---------------- Agg2 + bias + log_softmax ---------------------------------
__global__ void __launch_bounds__(256) k_agg2(const float* __restrict__ b2,
                                              float* __restrict__ out) {
    int i = blockIdx.x * blockDim.x + threadIdx.x;
    if (i >= N_NODES) return;

    float a0 = 0.f, a1 = 0.f, a2 = 0.f, a3 = 0.f, a4 = 0.f, a5 = 0.f, a6 = 0.f;

    int beg = g_rowptr[i], end = g_rowptr[i + 1];
    const int* __restrict__ colp = g_col;
#pragma unroll 2
    for (int e = beg; e < end; e++) {
        int s = __ldg(colp + e);
        const float4* p = (const float4*)(g_h2 + (size_t)s * H2W);
        float4 A = __ldg(p);
        float4 B = __ldg(p + 1);
        a0 += A.x; a1 += A.y; a2 += A.z; a3 += A.w;
        a4 += B.x; a5 += B.y; a6 += B.z;
    }
    {
        const float4* p = (const float4*)(g_h2 + (size_t)i * H2W);
        float4 A = *p;
        float4 B = *(p + 1);
        a0 += A.x; a1 += A.y; a2 += A.z; a3 += A.w;
        a4 += B.x; a5 += B.y; a6 += B.z;
    }
    float di = g_dis[i];
    float v[N_CLS];
    v[0] = fmaf(di, a0, __ldg(b2 + 0));
    v[1] = fmaf(di, a1, __ldg(b2 + 1));
    v[2] = fmaf(di, a2, __ldg(b2 + 2));
    v[3] = fmaf(di, a3, __ldg(b2 + 3));
    v[4] = fmaf(di, a4, __ldg(b2 + 4));
    v[5] = fmaf(di, a5, __ldg(b2 + 5));
    v[6] = fmaf(di, a6, __ldg(b2 + 6));

    float m = v[0];
#pragma unroll
    for (int k = 1; k < N_CLS; k++) m = fmaxf(m, v[k]);
    float s = 0.f;
#pragma unroll
    for (int k = 0; k < N_CLS; k++) s += expf(v[k] - m);
    float lse = m + logf(s);
#pragma unroll
    for (int k = 0; k < N_CLS; k++) out[(size_t)i * N_CLS + k] = v[k] - lse;
}

// ---------------- launch -----------------------------------------------------
extern "C" void kernel_launch(void* const* d_in, const int* in_sizes, int n_in,
                              void* d_out, int out_size) {
    const float* x  = (const float*)d_in[0];
    const int*   ei = (const int*)d_in[1];
    const float* W1 = (const float*)d_in[2];
    const float* b1 = (const float*)d_in[3];
    const float* W2 = (const float*)d_in[4];
    const float* b2 = (const float*)d_in[5];
    float* out = (float*)d_out;

    const int* src = ei;
    const int* dst = ei + N_EDGES;

    cudaFuncSetAttribute(k_gemm_mma, cudaFuncAttributeMaxDynamicSharedMemorySize, SMEM_GEMM);

    k_setup<<<(N_NODES + 255) / 256, 256>>>(W1);                   // 0
    k_count<<<(N_EDGES + 255) / 256, 256>>>(dst);                  // 1
    k_scan1<<<SCAN_BLOCKS, 1024>>>();                              // 2
    k_scan3m<<<SCAN_BLOCKS, 1024>>>();                             // 3
    k_fill<<<(N_EDGES + 511) / 512, 512>>>(src, dst);              // 4
    k_gemm_mma<<<(N_NODES + 127) / 128, 256, SMEM_GEMM>>>(x);      // 5
    k_agg1<<<(N_NODES + 7) / 8, 256>>>(b1, W2);                    // 6
    k_agg2<<<(N_NODES + 255) / 256, 256>>>(b2, out);               // 7
}

// round 14
// speedup vs baseline: 1.3690x; 1.2677x over previous
#include <cuda_runtime.h>
#include <cuda_bf16.h>
#include <cuda_fp16.h>
#include <math.h>
#include <stdint.h>

#define N_NODES 100000
#define N_EDGES 1600000
#define F_IN 512
#define HID 156
#define N_CLS 7
#define NPAD 160
#define NP2 80          // half2 pairs per row
#define H2W 8           // padded row width of g_h2

// ---------------- scratch (device globals; no allocation allowed) ----------
__device__ __align__(16) __half g_h16[(size_t)N_NODES * NPAD];   // 32 MB, dis-scaled
__device__ __align__(16) float g_h2[(size_t)N_NODES * H2W];      // 3.2 MB, dis-scaled
__device__ float g_dis[N_NODES];
__device__ int   g_deg[N_NODES];
__device__ int   g_rowptr[N_NODES + 1];
__device__ int   g_cursor[N_NODES];
__device__ int   g_col[N_EDGES];
__device__ int   g_blocksums[128];
__device__ unsigned g_ticket;
__device__ __align__(16) __nv_bfloat16 g_wt[NPAD * F_IN];   // W1^T bf16, [160][512]

#define SCAN_BLOCKS ((N_NODES + 1023) / 1024)    // 98

// ---------------- setup: W1 transpose/bf16 + deg init + ticket reset --------
// NOTE: grid must cover max(NPAD*F_IN, N_NODES) elements (both ranges guarded).
__global__ void k_setup(const float* __restrict__ W1) {
    int idx = blockIdx.x * 256 + threadIdx.x;
    if (idx == 0) g_ticket = 0;
    if (idx < NPAD * F_IN) {
        int n = idx >> 9;
        int k = idx & 511;
        float v = (n < HID) ? W1[(size_t)k * HID + n] : 0.f;
        g_wt[idx] = __float2bfloat16(v);
    }
    if (idx < N_NODES) g_deg[idx] = 1;
}

// ---------------- degree / CSR build ---------------------------------------
__global__ void k_count(const int* __restrict__ dst) {
    int e = blockIdx.x * blockDim.x + threadIdx.x;
    if (e < N_EDGES) atomicAdd(&g_deg[__ldg(dst + e)], 1);
}

// scan1: per-block inclusive scan; LAST block also exclusive-scans blocksums
__global__ void k_scan1() {
    __shared__ int sh[1024];
    __shared__ int isLast;
    int t = threadIdx.x;
    int i = blockIdx.x * 1024 + t;
    int v = (i < N_NODES) ? (g_deg[i] - 1) : 0;
    sh[t] = v;
    __syncthreads();
    for (int off = 1; off < 1024; off <<= 1) {
        int add = (t >= off) ? sh[t - off] : 0;
        __syncthreads();
        sh[t] += add;
        __syncthreads();
    }
    int incl = sh[t];
    if (i < N_NODES) g_rowptr[i] = incl - v;      // exclusive within block
    if (t == 1023) g_blocksums[blockIdx.x] = incl;
    __threadfence();
    if (t == 0) isLast = (atomicAdd(&g_ticket, 1) == gridDim.x - 1) ? 1 : 0;
    __syncthreads();
    if (isLast) {
        int bv = 0;
        if (t < 128) {
            bv = (t < SCAN_BLOCKS) ? __ldcg(&g_blocksums[t]) : 0;
            sh[t] = bv;
        }
        __syncthreads();
        for (int off = 1; off < 128; off <<= 1) {
            int add = (t >= off && t < 128) ? sh[t - off] : 0;
            __syncthreads();
            if (t < 128) sh[t] += add;
            __syncthreads();
        }
        if (t < SCAN_BLOCKS) g_blocksums[t] = sh[t] - bv;   // exclusive prefix
    }
}

// scan3m: elementwise add of pre-scanned blocksums + dis + cursor
__global__ void k_scan3m() {
    int i = blockIdx.x * 1024 + threadIdx.x;
    if (i < N_NODES) {
        int r = g_rowptr[i] + g_blocksums[i >> 10];
        g_rowptr[i] = r;
        g_cursor[i] = r;
        g_dis[i] = rsqrtf((float)g_deg[i]);
        if (i == 0) g_rowptr[N_NODES] = N_EDGES;
    }
}

__global__ void k_fill(const int* __restrict__ src, const int* __restrict__ dst) {
    int e = blockIdx.x * blockDim.x + threadIdx.x;
    if (e < N_EDGES) {
        int d = __ldg(dst + e);
        int pos = atomicAdd(&g_cursor[d], 1);
        g_col[pos] = __ldg(src + e);
    }
}

// ---------------- GEMM1: plain bf16 mma.sync + ldmatrix, double-buffered ----
// CTA: 128(M) x 160(N) x 512(K). 8 warps = 4(M) x 2(N). Single-MMA (no split).
// Stage: A[128][40] 10240 B + B[160][40] 12800 B = 23040 B; two stages.
// Epilogue reuses smem as Hs[128][84] u32 = 43008 B.
#define STAGE 23040
#define B_OFF 10240
#define SMEM_GEMM 46080

__device__ __forceinline__ void mma16816(float* d, const uint32_t* a,
                                         uint32_t b0, uint32_t b1) {
    asm volatile(
        "mma.sync.aligned.m16n8k16.row.col.f32.bf16.bf16.f32 "
        "{%0,%1,%2,%3}, {%4,%5,%6,%7}, {%8,%9}, {%0,%1,%2,%3};"
        : "+f"(d[0]), "+f"(d[1]), "+f"(d[2]), "+f"(d[3])
        : "r"(a[0]), "r"(a[1]), "r"(a[2]), "r"(a[3]), "r"(b0), "r"(b1));
}
#define LDSM4(r, addr) \
    asm volatile("ldmatrix.sync.aligned.m8n8.x4.shared.b16 {%0,%1,%2,%3}, [%4];" \
        : "=r"((r)[0]), "=r"((r)[1]), "=r"((r)[2]), "=r"((r)[3]) : "r"(addr))

__global__ void __launch_bounds__(256) k_gemm_mma(const float* __restrict__ x) {
    extern __shared__ char smem[];
    int tid = threadIdx.x, wid = tid >> 5, lane = tid & 31;
    int g = lane >> 2, tg = lane & 3;
    int wm = wid & 3, wn = wid >> 2;
    int bm = blockIdx.x * 128;

    uint32_t sbase = (uint32_t)__cvta_generic_to_shared(smem);
    int l8 = lane & 7;
    int aRow = l8 + ((lane >> 3) & 1) * 8;
    int aCol = (lane >= 16) ? 16 : 0;
    uint32_t aAddr = sbase + (uint32_t)(wm * 32 + aRow) * 80 + aCol;
    int bRow = l8 + ((lane >> 4) & 1) * 8;
    int bCol = ((lane >> 3) & 1) * 16;
    uint32_t bAddr = sbase + B_OFF + (uint32_t)(wn * 80 + bRow) * 80 + bCol;

    float acc[2][10][4];
#pragma unroll
    for (int i = 0; i < 2; i++)
#pragma unroll
        for (int j = 0; j < 10; j++)
#pragma unroll
            for (int q = 0; q < 4; q++) acc[i][j][q] = 0.f;

    float4 pa[4];
    uint2  pb[5];

    // ---- prefetch + store chunk 0 into buffer 0 ----
#pragma unroll
    for (int j = 0; j < 4; j++) {
        int idx = tid + j * 256;
        int r = idx >> 3, f4 = idx & 7;
        pa[j] = make_float4(0.f, 0.f, 0.f, 0.f);
        if (bm + r < N_NODES)
            pa[j] = *(const float4*)(x + (size_t)(bm + r) * F_IN + f4 * 4);
    }
#pragma unroll
    for (int j = 0; j < 5; j++) {
        int idx = tid + j * 256;
        int n = idx >> 3, q = idx & 7;
        pb[j] = *(const uint2*)((const char*)g_wt + (size_t)n * 1024 + q * 8);
    }
#pragma unroll
    for (int j = 0; j < 4; j++) {
        int idx = tid + j * 256;
        int r = idx >> 3, f4 = idx & 7;
        float4 v = pa[j];
        __nv_bfloat162 h01 = __floats2bfloat162_rn(v.x, v.y);
        __nv_bfloat162 h23 = __floats2bfloat162_rn(v.z, v.w);
        uint2 hw;
        hw.x = *(uint32_t*)&h01; hw.y = *(uint32_t*)&h23;
        *(uint2*)(smem + r * 80 + f4 * 8) = hw;
    }
#pragma unroll
    for (int j = 0; j < 5; j++) {
        int idx = tid + j * 256;
        int n = idx >> 3, q = idx & 7;
        *(uint2*)(smem + B_OFF + n * 80 + q * 8) = pb[j];
    }
    __syncthreads();

#pragma unroll 1
    for (int c = 0; c < 16; c++) {
        uint32_t cur = (c & 1) * STAGE;
        if (c + 1 < 16) {
            int k0 = (c + 1) * 32;
#pragma unroll
            for (int j = 0; j < 4; j++) {
                int idx = tid + j * 256;
                int r = idx >> 3, f4 = idx & 7;
                pa[j] = make_float4(0.f, 0.f, 0.f, 0.f);
                if (bm + r < N_NODES)
                    pa[j] = *(const float4*)(x + (size_t)(bm + r) * F_IN + k0 + f4 * 4);
            }
#pragma unroll
            for (int j = 0; j < 5; j++) {
                int idx = tid + j * 256;
                int n = idx >> 3, q = idx & 7;
                pb[j] = *(const uint2*)((const char*)g_wt + (size_t)n * 1024 + k0 * 2 + q * 8);
            }
        }

        // compute on current buffer
#pragma unroll
        for (int kk = 0; kk < 2; kk++) {
            int kb = kk * 32;
            uint32_t ah[2][4];
#pragma unroll
            for (int mf = 0; mf < 2; mf++)
                LDSM4(ah[mf], aAddr + cur + mf * 1280 + kb);
#pragma unroll
            for (int pnf = 0; pnf < 5; pnf++) {
                uint32_t bh[4];
                LDSM4(bh, bAddr + cur + pnf * 1280 + kb);
#pragma unroll
                for (int mf = 0; mf < 2; mf++) {
                    mma16816(acc[mf][2 * pnf],     ah[mf], bh[0], bh[1]);
                    mma16816(acc[mf][2 * pnf + 1], ah[mf], bh[2], bh[3]);
                }
            }
        }

        // store next chunk into the other buffer
        if (c + 1 < 16) {
            uint32_t nxt = ((c + 1) & 1) * STAGE;
#pragma unroll
            for (int j = 0; j < 4; j++) {
                int idx = tid + j * 256;
                int r = idx >> 3, f4 = idx & 7;
                float4 v = pa[j];
                __nv_bfloat162 h01 = __floats2bfloat162_rn(v.x, v.y);
                __nv_bfloat162 h23 = __floats2bfloat162_rn(v.z, v.w);
                uint2 hw;
                hw.x = *(uint32_t*)&h01; hw.y = *(uint32_t*)&h23;
                *(uint2*)(smem + nxt + r * 80 + f4 * 8) = hw;
            }
#pragma unroll
            for (int j = 0; j < 5; j++) {
                int idx = tid + j * 256;
                int n = idx >> 3, q = idx & 7;
                *(uint2*)(smem + nxt + B_OFF + n * 80 + q * 8) = pb[j];
            }
        }
        __syncthreads();
    }

    // ---- epilogue: scale by dis, half2 pack -> smem Hs[128][84] -> uint4 ----
    uint32_t* Hs = (uint32_t*)smem;
#pragma unroll
    for (int mf = 0; mf < 2; mf++) {
        int r = wm * 32 + mf * 16 + g;
        float d0 = (bm + r < N_NODES) ? g_dis[bm + r] : 0.f;
        float d8 = (bm + r + 8 < N_NODES) ? g_dis[bm + r + 8] : 0.f;
#pragma unroll
        for (int nf = 0; nf < 10; nf++) {
            int p = wn * 40 + nf * 4 + tg;
            __half2 v0 = __floats2half2_rn(acc[mf][nf][0] * d0, acc[mf][nf][1] * d0);
            __half2 v8 = __floats2half2_rn(acc[mf][nf][2] * d8, acc[mf][nf][3] * d8);
            Hs[r * 84 + p]       = *(uint32_t*)&v0;
            Hs[(r + 8) * 84 + p] = *(uint32_t*)&v8;
        }
    }
    __syncthreads();

    int rows = N_NODES - bm;
    if (rows > 128) rows = 128;
    int total4 = rows * 20;
    for (int i = tid; i < total4; i += 256) {
        int r = i / 20, q = i - r * 20;
        uint4 v = *(uint4*)&Hs[r * 84 + q * 4];
        *(uint4*)((char*)g_h16 + (size_t)(bm + r) * 320 + q * 16) = v;
    }
}

// ---------------- Agg1: gather dis-scaled h (fp16) + relu + W2 projection ---
__global__ void __launch_bounds__(256) k_agg1(const float* __restrict__ b1,
                                              const float* __restrict__ W2) {
    __shared__ float2 W2p[96 * N_CLS];
    __shared__ float2 b1p[96];
    int tid = threadIdx.x;
    for (int i = tid; i < 96 * N_CLS; i += 256) {
        int p = i / N_CLS, k = i - p * N_CLS;
        float lo = (2 * p < HID) ? W2[(2 * p) * N_CLS + k] : 0.f;
        float hi = (2 * p + 1 < HID) ? W2[(2 * p + 1) * N_CLS + k] : 0.f;
        W2p[i] = make_float2(lo, hi);
    }
    for (int p = tid; p < 96; p += 256) {
        float lo = (2 * p < HID) ? b1[2 * p] : 0.f;
        float hi = (2 * p + 1 < HID) ? b1[2 * p + 1] : 0.f;
        b1p[p] = make_float2(lo, hi);
    }
    __syncthreads();

    int warp = tid >> 5, lane = tid & 31;
    int node = blockIdx.x * 8 + warp;
    if (node >= N_NODES) return;

    float2 a0 = make_float2(0.f, 0.f), a1 = a0, a2 = a0;
    int beg = g_rowptr[node], end = g_rowptr[node + 1];
    const uint32_t* __restrict__ hbase = (const uint32_t*)g_h16;
    const int* __restrict__ colp = g_col;
#pragma unroll 4
    for (int e = beg; e < end; e++) {
        int s = __ldg(colp + e);
        const uint32_t* hp = hbase + (size_t)s * NP2;
        uint32_t w0 = __ldg(hp + lane);
        uint32_t w1 = __ldg(hp + lane + 32);
        uint32_t w2 = (lane < 16) ? __ldg(hp + lane + 64) : 0u;
        float2 f0 = __half22float2(*(__half2*)&w0);
        float2 f1 = __half22float2(*(__half2*)&w1);
        float2 f2 = __half22float2(*(__half2*)&w2);
        a0.x += f0.x; a0.y += f0.y;
        a1.x += f1.x; a1.y += f1.y;
        a2.x += f2.x; a2.y += f2.y;
    }
    {
        const uint32_t* hp = hbase + (size_t)node * NP2;
        uint32_t w0 = hp[lane];
        uint32_t w1 = hp[lane + 32];
        uint32_t w2 = (lane < 16) ? hp[lane + 64] : 0u;
        float2 f0 = __half22float2(*(__half2*)&w0);
        float2 f1 = __half22float2(*(__half2*)&w1);
        float2 f2 = __half22float2(*(__half2*)&w2);
        a0.x += f0.x; a0.y += f0.y;
        a1.x += f1.x; a1.y += f1.y;
        a2.x += f2.x; a2.y += f2.y;
    }
    float di = g_dis[node];
    float2 bb0 = b1p[lane], bb1 = b1p[lane + 32], bb2 = b1p[lane + 64];
    float2 u0 = make_float2(fmaxf(fmaf(di, a0.x, bb0.x), 0.f),
                            fmaxf(fmaf(di, a0.y, bb0.y), 0.f));
    float2 u1 = make_float2(fmaxf(fmaf(di, a1.x, bb1.x), 0.f),
                            fmaxf(fmaf(di, a1.y, bb1.y), 0.f));
    float2 u2 = make_float2(fmaxf(fmaf(di, a2.x, bb2.x), 0.f),
                            fmaxf(fmaf(di, a2.y, bb2.y), 0.f));
    if (lane >= 16) { u2.x = 0.f; u2.y = 0.f; }

    float outk[N_CLS];
#pragma unroll
    for (int k = 0; k < N_CLS; k++) {
        float2 w0 = W2p[lane * N_CLS + k];
        float2 w1 = W2p[(lane + 32) * N_CLS + k];
        float2 w2 = W2p[(lane + 64) * N_CLS + k];
        float p = u0.x * w0.x + u0.y * w0.y
                + u1.x * w1.x + u1.y * w1.y
                + u2.x * w2.x + u2.y * w2.y;
#pragma unroll
        for (int o = 16; o > 0; o >>= 1) p += __shfl_xor_sync(0xffffffffu, p, o);
        outk[k] = p;
    }
    if (lane == 0) {
#pragma unroll
        for (int k = 0; k < N_CLS; k++)
            g_h2[(size_t)node * H2W + k] = di * outk[k];
    }
}

// ---------------- Agg2 + bias + log_softmax ---------------------------------
__global__ void __launch_bounds__(256) k_agg2(const float* __restrict__ b2,
                                              float* __restrict__ out) {
    int i = blockIdx.x * blockDim.x + threadIdx.x;
    if (i >= N_NODES) return;

    float a0 = 0.f, a1 = 0.f, a2 = 0.f, a3 = 0.f, a4 = 0.f, a5 = 0.f, a6 = 0.f;

    int beg = g_rowptr[i], end = g_rowptr[i + 1];
    const int* __restrict__ colp = g_col;
#pragma unroll 2
    for (int e = beg; e < end; e++) {
        int s = __ldg(colp + e);
        const float4* p = (const float4*)(g_h2 + (size_t)s * H2W);
        float4 A = __ldg(p);
        float4 B = __ldg(p + 1);
        a0 += A.x; a1 += A.y; a2 += A.z; a3 += A.w;
        a4 += B.x; a5 += B.y; a6 += B.z;
    }
    {
        const float4* p = (const float4*)(g_h2 + (size_t)i * H2W);
        float4 A = *p;
        float4 B = *(p + 1);
        a0 += A.x; a1 += A.y; a2 += A.z; a3 += A.w;
        a4 += B.x; a5 += B.y; a6 += B.z;
    }
    float di = g_dis[i];
    float v[N_CLS];
    v[0] = fmaf(di, a0, __ldg(b2 + 0));
    v[1] = fmaf(di, a1, __ldg(b2 + 1));
    v[2] = fmaf(di, a2, __ldg(b2 + 2));
    v[3] = fmaf(di, a3, __ldg(b2 + 3));
    v[4] = fmaf(di, a4, __ldg(b2 + 4));
    v[5] = fmaf(di, a5, __ldg(b2 + 5));
    v[6] = fmaf(di, a6, __ldg(b2 + 6));

    float m = v[0];
#pragma unroll
    for (int k = 1; k < N_CLS; k++) m = fmaxf(m, v[k]);
    float s = 0.f;
#pragma unroll
    for (int k = 0; k < N_CLS; k++) s += expf(v[k] - m);
    float lse = m + logf(s);
#pragma unroll
    for (int k = 0; k < N_CLS; k++) out[(size_t)i * N_CLS + k] = v[k] - lse;
}

// ---------------- launch -----------------------------------------------------
extern "C" void kernel_launch(void* const* d_in, const int* in_sizes, int n_in,
                              void* d_out, int out_size) {
    const float* x  = (const float*)d_in[0];
    const int*   ei = (const int*)d_in[1];
    const float* W1 = (const float*)d_in[2];
    const float* b1 = (const float*)d_in[3];
    const float* W2 = (const float*)d_in[4];
    const float* b2 = (const float*)d_in[5];
    float* out = (float*)d_out;

    const int* src = ei;
    const int* dst = ei + N_EDGES;

    cudaFuncSetAttribute(k_gemm_mma, cudaFuncAttributeMaxDynamicSharedMemorySize, SMEM_GEMM);

    // k_setup grid MUST cover N_NODES (deg init), not just NPAD*F_IN
    k_setup<<<(N_NODES + 255) / 256, 256>>>(W1);                   // 0
    k_count<<<(N_EDGES + 255) / 256, 256>>>(dst);                  // 1
    k_scan1<<<SCAN_BLOCKS, 1024>>>();                              // 2
    k_scan3m<<<SCAN_BLOCKS, 1024>>>();                             // 3
    k_fill<<<(N_EDGES + 511) / 512, 512>>>(src, dst);              // 4
    k_gemm_mma<<<(N_NODES + 127) / 128, 256, SMEM_GEMM>>>(x);      // 5
    k_agg1<<<(N_NODES + 7) / 8, 256>>>(b1, W2);                    // 6
    k_agg2<<<(N_NODES + 255) / 256, 256>>>(b2, out);               // 7
}

// round 15
// speedup vs baseline: 1.4488x; 1.0583x over previous
#include <cuda_runtime.h>
#include <cuda_bf16.h>
#include <cuda_fp16.h>
#include <math.h>
#include <stdint.h>

#define N_NODES 100000
#define N_EDGES 1600000
#define F_IN 512
#define HID 156
#define N_CLS 7
#define NPAD 160
#define NP2 80          // half2 pairs per row
#define H2W 8           // padded row width of g_h2

// ---------------- scratch (device globals; no allocation allowed) ----------
__device__ __align__(16) __half g_h16[(size_t)N_NODES * NPAD];   // 32 MB, UNscaled
__device__ __align__(16) float g_h2[(size_t)N_NODES * H2W];      // 3.2 MB, dis-scaled
__device__ float g_dis[N_NODES];
__device__ int   g_deg[N_NODES];
__device__ int   g_rowptr[N_NODES + 1];
__device__ int   g_cursor[N_NODES];
__device__ int   g_col[N_EDGES];
__device__ int   g_blocksums[128];
__device__ int   g_blockpfx[128];
__device__ unsigned g_ticket;
__device__ volatile int g_flag;
__device__ __align__(16) __nv_bfloat16 g_wt[NPAD * F_IN];   // W1^T bf16, [160][512]

#define SCAN_BLOCKS ((N_NODES + 1023) / 1024)    // 98

// ---------------- setup: W1 transpose/bf16 + deg init + sync resets ---------
__global__ void k_setup(const float* __restrict__ W1) {
    int idx = blockIdx.x * 256 + threadIdx.x;
    if (idx == 0) { g_ticket = 0; g_flag = 0; }
    if (idx < NPAD * F_IN) {
        int n = idx >> 9;
        int k = idx & 511;
        float v = (n < HID) ? W1[(size_t)k * HID + n] : 0.f;
        g_wt[idx] = __float2bfloat16(v);
    }
    if (idx < N_NODES) g_deg[idx] = 1;
}

// ---------------- degree / CSR build ---------------------------------------
__global__ void k_count(const int* __restrict__ dst) {
    int e = blockIdx.x * blockDim.x + threadIdx.x;
    if (e < N_EDGES) atomicAdd(&g_deg[__ldg(dst + e)], 1);
}

// merged scan: per-block scan + last-block blocksum scan + grid-wide flag sync
__global__ void k_scan1m() {
    __shared__ int sh[1024];
    __shared__ int isLast;
    int t = threadIdx.x, b = blockIdx.x;
    int i = b * 1024 + t;
    int v = (i < N_NODES) ? (g_deg[i] - 1) : 0;
    sh[t] = v;
    __syncthreads();
    for (int off = 1; off < 1024; off <<= 1) {
        int add = (t >= off) ? sh[t - off] : 0;
        __syncthreads();
        sh[t] += add;
        __syncthreads();
    }
    int excl = sh[t] - v;                     // exclusive within block
    if (t == 1023) g_blocksums[b] = sh[t];
    __threadfence();
    if (t == 0) isLast = (atomicAdd(&g_ticket, 1) == gridDim.x - 1) ? 1 : 0;
    __syncthreads();
    if (isLast) {
        int bv = 0;
        if (t < 128) bv = (t < SCAN_BLOCKS) ? __ldcg(&g_blocksums[t]) : 0;
        __syncthreads();
        if (t < 128) sh[t] = bv;
        __syncthreads();
        for (int off = 1; off < 128; off <<= 1) {
            int add = (t >= off && t < 128) ? sh[t - off] : 0;
            __syncthreads();
            if (t < 128) sh[t] += add;
            __syncthreads();
        }
        if (t < SCAN_BLOCKS) g_blockpfx[t] = sh[t] - bv;   // exclusive prefix
        __threadfence();
        __syncthreads();
        if (t == 0) g_flag = 1;
    }
    if (t == 0) { while (g_flag == 0) __nanosleep(64); }
    __syncthreads();
    __threadfence();
    int base = __ldcg((const int*)&g_blockpfx[b]);
    if (i < N_NODES) {
        int r = excl + base;
        g_rowptr[i] = r;
        g_cursor[i] = r;
        g_dis[i] = rsqrtf((float)g_deg[i]);
        if (i == 0) g_rowptr[N_NODES] = N_EDGES;
    }
}

__global__ void k_fill(const int* __restrict__ src, const int* __restrict__ dst) {
    int e = blockIdx.x * blockDim.x + threadIdx.x;
    if (e < N_EDGES) {
        int d = __ldg(dst + e);
        int pos = atomicAdd(&g_cursor[d], 1);
        g_col[pos] = __ldg(src + e);
    }
}

// ---------------- GEMM1: plain bf16 mma.sync + ldmatrix, double-buffered ----
// CTA: 128(M) x 160(N) x 512(K). 8 warps = 4(M) x 2(N). Unscaled fp16 output.
#define STAGE 23040
#define B_OFF 10240
#define SMEM_GEMM 46080

__device__ __forceinline__ void mma16816(float* d, const uint32_t* a,
                                         uint32_t b0, uint32_t b1) {
    asm volatile(
        "mma.sync.aligned.m16n8k16.row.col.f32.bf16.bf16.f32 "
        "{%0,%1,%2,%3}, {%4,%5,%6,%7}, {%8,%9}, {%0,%1,%2,%3};"
        : "+f"(d[0]), "+f"(d[1]), "+f"(d[2]), "+f"(d[3])
        : "r"(a[0]), "r"(a[1]), "r"(a[2]), "r"(a[3]), "r"(b0), "r"(b1));
}
#define LDSM4(r, addr) \
    asm volatile("ldmatrix.sync.aligned.m8n8.x4.shared.b16 {%0,%1,%2,%3}, [%4];" \
        : "=r"((r)[0]), "=r"((r)[1]), "=r"((r)[2]), "=r"((r)[3]) : "r"(addr))

__global__ void __launch_bounds__(256) k_gemm_mma(const float* __restrict__ x) {
    extern __shared__ char smem[];
    int tid = threadIdx.x, wid = tid >> 5, lane = tid & 31;
    int g = lane >> 2, tg = lane & 3;
    int wm = wid & 3, wn = wid >> 2;
    int bm = blockIdx.x * 128;

    uint32_t sbase = (uint32_t)__cvta_generic_to_shared(smem);
    int l8 = lane & 7;
    int aRow = l8 + ((lane >> 3) & 1) * 8;
    int aCol = (lane >= 16) ? 16 : 0;
    uint32_t aAddr = sbase + (uint32_t)(wm * 32 + aRow) * 80 + aCol;
    int bRow = l8 + ((lane >> 4) & 1) * 8;
    int bCol = ((lane >> 3) & 1) * 16;
    uint32_t bAddr = sbase + B_OFF + (uint32_t)(wn * 80 + bRow) * 80 + bCol;

    float acc[2][10][4];
#pragma unroll
    for (int i = 0; i < 2; i++)
#pragma unroll
        for (int j = 0; j < 10; j++)
#pragma unroll
            for (int q = 0; q < 4; q++) acc[i][j][q] = 0.f;

    float4 pa[4];
    uint2  pb[5];

    // ---- prefetch + store chunk 0 into buffer 0 ----
#pragma unroll
    for (int j = 0; j < 4; j++) {
        int idx = tid + j * 256;
        int r = idx >> 3, f4 = idx & 7;
        pa[j] = make_float4(0.f, 0.f, 0.f, 0.f);
        if (bm + r < N_NODES)
            pa[j] = *(const float4*)(x + (size_t)(bm + r) * F_IN + f4 * 4);
    }
#pragma unroll
    for (int j = 0; j < 5; j++) {
        int idx = tid + j * 256;
        int n = idx >> 3, q = idx & 7;
        pb[j] = *(const uint2*)((const char*)g_wt + (size_t)n * 1024 + q * 8);
    }
#pragma unroll
    for (int j = 0; j < 4; j++) {
        int idx = tid + j * 256;
        int r = idx >> 3, f4 = idx & 7;
        float4 v = pa[j];
        __nv_bfloat162 h01 = __floats2bfloat162_rn(v.x, v.y);
        __nv_bfloat162 h23 = __floats2bfloat162_rn(v.z, v.w);
        uint2 hw;
        hw.x = *(uint32_t*)&h01; hw.y = *(uint32_t*)&h23;
        *(uint2*)(smem + r * 80 + f4 * 8) = hw;
    }
#pragma unroll
    for (int j = 0; j < 5; j++) {
        int idx = tid + j * 256;
        int n = idx >> 3, q = idx & 7;
        *(uint2*)(smem + B_OFF + n * 80 + q * 8) = pb[j];
    }
    __syncthreads();

#pragma unroll 1
    for (int c = 0; c < 16; c++) {
        uint32_t cur = (c & 1) * STAGE;
        if (c + 1 < 16) {
            int k0 = (c + 1) * 32;
#pragma unroll
            for (int j = 0; j < 4; j++) {
                int idx = tid + j * 256;
                int r = idx >> 3, f4 = idx & 7;
                pa[j] = make_float4(0.f, 0.f, 0.f, 0.f);
                if (bm + r < N_NODES)
                    pa[j] = *(const float4*)(x + (size_t)(bm + r) * F_IN + k0 + f4 * 4);
            }
#pragma unroll
            for (int j = 0; j < 5; j++) {
                int idx = tid + j * 256;
                int n = idx >> 3, q = idx & 7;
                pb[j] = *(const uint2*)((const char*)g_wt + (size_t)n * 1024 + k0 * 2 + q * 8);
            }
        }

#pragma unroll
        for (int kk = 0; kk < 2; kk++) {
            int kb = kk * 32;
            uint32_t ah[2][4];
#pragma unroll
            for (int mf = 0; mf < 2; mf++)
                LDSM4(ah[mf], aAddr + cur + mf * 1280 + kb);
#pragma unroll
            for (int pnf = 0; pnf < 5; pnf++) {
                uint32_t bh[4];
                LDSM4(bh, bAddr + cur + pnf * 1280 + kb);
#pragma unroll
                for (int mf = 0; mf < 2; mf++) {
                    mma16816(acc[mf][2 * pnf],     ah[mf], bh[0], bh[1]);
                    mma16816(acc[mf][2 * pnf + 1], ah[mf], bh[2], bh[3]);
                }
            }
        }

        if (c + 1 < 16) {
            uint32_t nxt = ((c + 1) & 1) * STAGE;
#pragma unroll
            for (int j = 0; j < 4; j++) {
                int idx = tid + j * 256;
                int r = idx >> 3, f4 = idx & 7;
                float4 v = pa[j];
                __nv_bfloat162 h01 = __floats2bfloat162_rn(v.x, v.y);
                __nv_bfloat162 h23 = __floats2bfloat162_rn(v.z, v.w);
                uint2 hw;
                hw.x = *(uint32_t*)&h01; hw.y = *(uint32_t*)&h23;
                *(uint2*)(smem + nxt + r * 80 + f4 * 8) = hw;
            }
#pragma unroll
            for (int j = 0; j < 5; j++) {
                int idx = tid + j * 256;
                int n = idx >> 3, q = idx & 7;
                *(uint2*)(smem + nxt + B_OFF + n * 80 + q * 8) = pb[j];
            }
        }
        __syncthreads();
    }

    // ---- epilogue: half2 pack (UNscaled) -> smem Hs[128][84] -> uint4 ----
    uint32_t* Hs = (uint32_t*)smem;
#pragma unroll
    for (int mf = 0; mf < 2; mf++) {
        int r = wm * 32 + mf * 16 + g;
#pragma unroll
        for (int nf = 0; nf < 10; nf++) {
            int p = wn * 40 + nf * 4 + tg;
            __half2 v0 = __floats2half2_rn(acc[mf][nf][0], acc[mf][nf][1]);
            __half2 v8 = __floats2half2_rn(acc[mf][nf][2], acc[mf][nf][3]);
            Hs[r * 84 + p]       = *(uint32_t*)&v0;
            Hs[(r + 8) * 84 + p] = *(uint32_t*)&v8;
        }
    }
    __syncthreads();

    int rows = N_NODES - bm;
    if (rows > 128) rows = 128;
    int total4 = rows * 20;
    for (int i = tid; i < total4; i += 256) {
        int r = i / 20, q = i - r * 20;
        uint4 v = *(uint4*)&Hs[r * 84 + q * 4];
        *(uint4*)((char*)g_h16 + (size_t)(bm + r) * 320 + q * 16) = v;
    }
}

// ---------------- Agg1: gather h (fp16) * dis[s] + relu + W2 projection -----
__global__ void __launch_bounds__(256) k_agg1(const float* __restrict__ b1,
                                              const float* __restrict__ W2) {
    __shared__ float2 W2p[96 * N_CLS];
    __shared__ float2 b1p[96];
    int tid = threadIdx.x;
    for (int i = tid; i < 96 * N_CLS; i += 256) {
        int p = i / N_CLS, k = i - p * N_CLS;
        float lo = (2 * p < HID) ? W2[(2 * p) * N_CLS + k] : 0.f;
        float hi = (2 * p + 1 < HID) ? W2[(2 * p + 1) * N_CLS + k] : 0.f;
        W2p[i] = make_float2(lo, hi);
    }
    for (int p = tid; p < 96; p += 256) {
        float lo = (2 * p < HID) ? b1[2 * p] : 0.f;
        float hi = (2 * p + 1 < HID) ? b1[2 * p + 1] : 0.f;
        b1p[p] = make_float2(lo, hi);
    }
    __syncthreads();

    int warp = tid >> 5, lane = tid & 31;
    int node = blockIdx.x * 8 + warp;
    if (node >= N_NODES) return;

    float2 a0 = make_float2(0.f, 0.f), a1 = a0, a2 = a0;
    int beg = g_rowptr[node], end = g_rowptr[node + 1];
    const uint32_t* __restrict__ hbase = (const uint32_t*)g_h16;
    const int* __restrict__ colp = g_col;
    const float* __restrict__ disp = g_dis;
#pragma unroll 4
    for (int e = beg; e < end; e++) {
        int s = __ldg(colp + e);
        float ds = __ldg(disp + s);
        const uint32_t* hp = hbase + (size_t)s * NP2;
        uint32_t w0 = __ldg(hp + lane);
        uint32_t w1 = __ldg(hp + lane + 32);
        uint32_t w2 = (lane < 16) ? __ldg(hp + lane + 64) : 0u;
        float2 f0 = __half22float2(*(__half2*)&w0);
        float2 f1 = __half22float2(*(__half2*)&w1);
        float2 f2 = __half22float2(*(__half2*)&w2);
        a0.x = fmaf(ds, f0.x, a0.x); a0.y = fmaf(ds, f0.y, a0.y);
        a1.x = fmaf(ds, f1.x, a1.x); a1.y = fmaf(ds, f1.y, a1.y);
        a2.x = fmaf(ds, f2.x, a2.x); a2.y = fmaf(ds, f2.y, a2.y);
    }
    float di = g_dis[node];
    {   // self term
        const uint32_t* hp = hbase + (size_t)node * NP2;
        uint32_t w0 = hp[lane];
        uint32_t w1 = hp[lane + 32];
        uint32_t w2 = (lane < 16) ? hp[lane + 64] : 0u;
        float2 f0 = __half22float2(*(__half2*)&w0);
        float2 f1 = __half22float2(*(__half2*)&w1);
        float2 f2 = __half22float2(*(__half2*)&w2);
        a0.x = fmaf(di, f0.x, a0.x); a0.y = fmaf(di, f0.y, a0.y);
        a1.x = fmaf(di, f1.x, a1.x); a1.y = fmaf(di, f1.y, a1.y);
        a2.x = fmaf(di, f2.x, a2.x); a2.y = fmaf(di, f2.y, a2.y);
    }
    float2 bb0 = b1p[lane], bb1 = b1p[lane + 32], bb2 = b1p[lane + 64];
    float2 u0 = make_float2(fmaxf(fmaf(di, a0.x, bb0.x), 0.f),
                            fmaxf(fmaf(di, a0.y, bb0.y), 0.f));
    float2 u1 = make_float2(fmaxf(fmaf(di, a1.x, bb1.x), 0.f),
                            fmaxf(fmaf(di, a1.y, bb1.y), 0.f));
    float2 u2 = make_float2(fmaxf(fmaf(di, a2.x, bb2.x), 0.f),
                            fmaxf(fmaf(di, a2.y, bb2.y), 0.f));
    if (lane >= 16) { u2.x = 0.f; u2.y = 0.f; }

    float outk[N_CLS];
#pragma unroll
    for (int k = 0; k < N_CLS; k++) {
        float2 w0 = W2p[lane * N_CLS + k];
        float2 w1 = W2p[(lane + 32) * N_CLS + k];
        float2 w2 = W2p[(lane + 64) * N_CLS + k];
        float p = u0.x * w0.x + u0.y * w0.y
                + u1.x * w1.x + u1.y * w1.y
                + u2.x * w2.x + u2.y * w2.y;
#pragma unroll
        for (int o = 16; o > 0; o >>= 1) p += __shfl_xor_sync(0xffffffffu, p, o);
        outk[k] = p;
    }
    if (lane == 0) {
#pragma unroll
        for (int k = 0; k < N_CLS; k++)
            g_h2[(size_t)node * H2W + k] = di * outk[k];   // dis-scaled for agg2
    }
}

// ---------------- Agg2 + bias + log_softmax ---------------------------------
__global__ void __launch_bounds__(256) k_agg2(const float* __restrict__ b2,
                                              float* __restrict__ out) {
    int i = blockIdx.x * blockDim.x + threadIdx.x;
    if (i >= N_NODES) return;

    float a0 = 0.f, a1 = 0.f, a2 = 0.f, a3 = 0.f, a4 = 0.f, a5 = 0.f, a6 = 0.f;

    int beg = g_rowptr[i], end = g_rowptr[i + 1];
    const int* __restrict__ colp = g_col;
#pragma unroll 2
    for (int e = beg; e < end; e++) {
        int s = __ldg(colp + e);
        const float4* p = (const float4*)(g_h2 + (size_t)s * H2W);
        float4 A = __ldg(p);
        float4 B = __ldg(p + 1);
        a0 += A.x; a1 += A.y; a2 += A.z; a3 += A.w;
        a4 += B.x; a5 += B.y; a6 += B.z;
    }
    {
        const float4* p = (const float4*)(g_h2 + (size_t)i * H2W);
        float4 A = *p;
        float4 B = *(p + 1);
        a0 += A.x; a1 += A.y; a2 += A.z; a3 += A.w;
        a4 += B.x; a5 += B.y; a6 += B.z;
    }
    float di = g_dis[i];
    float v[N_CLS];
    v[0] = fmaf(di, a0, __ldg(b2 + 0));
    v[1] = fmaf(di, a1, __ldg(b2 + 1));
    v[2] = fmaf(di, a2, __ldg(b2 + 2));
    v[3] = fmaf(di, a3, __ldg(b2 + 3));
    v[4] = fmaf(di, a4, __ldg(b2 + 4));
    v[5] = fmaf(di, a5, __ldg(b2 + 5));
    v[6] = fmaf(di, a6, __ldg(b2 + 6));

    float m = v[0];
#pragma unroll
    for (int k = 1; k < N_CLS; k++) m = fmaxf(m, v[k]);
    float s = 0.f;
#pragma unroll
    for (int k = 0; k < N_CLS; k++) s += expf(v[k] - m);
    float lse = m + logf(s);
#pragma unroll
    for (int k = 0; k < N_CLS; k++) out[(size_t)i * N_CLS + k] = v[k] - lse;
}

// ---------------- launch: forked streams under graph capture ----------------
extern "C" void kernel_launch(void* const* d_in, const int* in_sizes, int n_in,
                              void* d_out, int out_size) {
    const float* x  = (const float*)d_in[0];
    const int*   ei = (const int*)d_in[1];
    const float* W1 = (const float*)d_in[2];
    const float* b1 = (const float*)d_in[3];
    const float* W2 = (const float*)d_in[4];
    const float* b2 = (const float*)d_in[5];
    float* out = (float*)d_out;

    const int* src = ei;
    const int* dst = ei + N_EDGES;

    static cudaStream_t s2 = nullptr;
    static cudaEvent_t evA = nullptr, evB = nullptr;
    if (!s2) {
        cudaStreamCreateWithFlags(&s2, cudaStreamNonBlocking);
        cudaEventCreateWithFlags(&evA, cudaEventDisableTiming);
        cudaEventCreateWithFlags(&evB, cudaEventDisableTiming);
        cudaFuncSetAttribute(k_gemm_mma, cudaFuncAttributeMaxDynamicSharedMemorySize, SMEM_GEMM);
    }

    // default stream: setup -> gemm   |   s2: count -> scan -> fill
    k_setup<<<(N_NODES + 255) / 256, 256>>>(W1);
    cudaEventRecord(evA, 0);
    cudaStreamWaitEvent(s2, evA, 0);
    k_count<<<(N_EDGES + 255) / 256, 256, 0, s2>>>(dst);
    k_scan1m<<<SCAN_BLOCKS, 1024, 0, s2>>>();
    k_fill<<<(N_EDGES + 511) / 512, 512, 0, s2>>>(src, dst);
    cudaEventRecord(evB, s2);

    k_gemm_mma<<<(N_NODES + 127) / 128, 256, SMEM_GEMM>>>(x);   // concurrent with s2

    cudaStreamWaitEvent(0, evB, 0);                             // rejoin
    k_agg1<<<(N_NODES + 7) / 8, 256>>>(b1, W2);
    k_agg2<<<(N_NODES + 255) / 256, 256>>>(b2, out);
}